// round 1
// baseline (speedup 1.0000x reference)
#include <cuda_runtime.h>

typedef unsigned long long ull;

// Problem constants
constexpr int BS = 16384, D = 100, H = 16, P = 2;
// Tiling
constexpr int TB_B = 32;   // batch rows per block
constexpr int TB_T = 20;   // variables (t) per block
constexpr int KC   = 20;   // j-chunk (reduction) size
constexpr int NTH  = 320;  // threads: ig(2) * bg(8) * tt(20)
constexpr int BPAD = 36;   // padded b-extent in smem (144B rows -> float4 aligned)

// Scratch: W0 transposed to [t][j][i] for coalesced chunk loads.
__device__ float g_W0T[D * D * H];

__global__ void transpose_w0_kernel(const float* __restrict__ W0) {
    int t = blockIdx.x;
    for (int e = threadIdx.x; e < D * H; e += blockDim.x) {
        int j = e >> 4, i = e & 15;           // e = j*16 + i
        g_W0T[t * (D * H) + e] = W0[t * (D * H) + i * D + j];
    }
}

struct Smem {
    float sX[TB_B][D];                 // 12800 B
    union {
        float sMX[KC][TB_T][BPAD];     // 57600 B : mx[j][t][b] = M*x masked
        float sH0[TB_T][H][BPAD];      // 46080 B : h0 transposed for layer-1
    } u;
    union {
        float sW0[TB_T][KC][H];        // 25600 B : W0 chunk [t][j][i]
        float sW1[TB_T][H][H];         // 20480 B : W1 slice [t][j][i]
    } w;
    float sB0[TB_T][H];                // 1280 B
    float sB1[TB_T][H];                // 1280 B
};

__device__ __forceinline__ ull pk2(float a, float b) {
    ull r; asm("mov.b64 %0, {%1, %2};" : "=l"(r) : "f"(a), "f"(b)); return r;
}
__device__ __forceinline__ void unpk2(ull v, float& a, float& b) {
    asm("mov.b64 {%0, %1}, %2;" : "=f"(a), "=f"(b) : "l"(v));
}
// Packed fp32x2 FMA (Blackwell FFMA2 — PTX-only form)
__device__ __forceinline__ ull ffma2(ull a, ull b, ull c) {
    ull d; asm("fma.rn.f32x2 %0, %1, %2, %3;" : "=l"(d) : "l"(a), "l"(b), "l"(c));
    return d;
}
__device__ __forceinline__ float lrelu(float v) { return v > 0.f ? v : 0.01f * v; }

// 4b x 8i micro-tile rank-1 update: acc[b][ipair] += w[i..i+1] * m[b]
__device__ __forceinline__ void fma_tile(ull (&acc)[4][4], const float4 mq,
                                         const float4 wq0, const float4 wq1) {
    ull w01 = pk2(wq0.x, wq0.y), w23 = pk2(wq0.z, wq0.w);
    ull w45 = pk2(wq1.x, wq1.y), w67 = pk2(wq1.z, wq1.w);
    ull m[4] = {pk2(mq.x, mq.x), pk2(mq.y, mq.y), pk2(mq.z, mq.z), pk2(mq.w, mq.w)};
#pragma unroll
    for (int b = 0; b < 4; ++b) {
        acc[b][0] = ffma2(w01, m[b], acc[b][0]);
        acc[b][1] = ffma2(w23, m[b], acc[b][1]);
        acc[b][2] = ffma2(w45, m[b], acc[b][2]);
        acc[b][3] = ffma2(w67, m[b], acc[b][3]);
    }
}

__global__ void __launch_bounds__(NTH, 2)
mlp_kernel(const float* __restrict__ x, const float* __restrict__ M,
           const float* __restrict__ W1g, const float* __restrict__ W2g,
           const float* __restrict__ b0g, const float* __restrict__ b1g,
           const float* __restrict__ b2g, float* __restrict__ out) {
    extern __shared__ char smem_raw[];
    Smem* s = reinterpret_cast<Smem*>(smem_raw);
    const int tid = threadIdx.x;
    const int ig = tid & 1;            // i-half: 0 -> i 0..7, 1 -> i 8..15
    const int bg = (tid >> 1) & 7;     // b-quad: b = 4*bg .. 4*bg+3
    const int tt = tid >> 4;           // local t (0..19)
    const int b0i = blockIdx.x * TB_B;
    const int t0  = blockIdx.y * TB_T;

    // ---- stage x tile + bias slices ----
    for (int e = tid; e < TB_B * D; e += NTH) {
        int b = e / D, j = e % D;
        s->sX[b][j] = x[(b0i + b) * D + j];
    }
    for (int e = tid; e < TB_T * H; e += NTH) {
        s->sB0[0][e] = b0g[t0 * H + e];
        s->sB1[0][e] = b1g[t0 * H + e];
    }
    __syncthreads();

    // ---- layer 0: h0[b,t,i] = sum_j W0[t,i,j] * M[b,j,t] * x[b,j] * (j!=t) + b0 ----
    ull acc[4][4];
    {
        ull bias[4];
#pragma unroll
        for (int ip = 0; ip < 4; ++ip)
            bias[ip] = pk2(s->sB0[tt][8 * ig + 2 * ip], s->sB0[tt][8 * ig + 2 * ip + 1]);
#pragma unroll
        for (int b = 0; b < 4; ++b)
#pragma unroll
            for (int ip = 0; ip < 4; ++ip) acc[b][ip] = bias[ip];
    }

    for (int kc = 0; kc < D; kc += KC) {
        __syncthreads();  // previous chunk's compute done before overwrite
        // W0 chunk: [tt][jj][i], contiguous from g_W0T
        for (int e = tid; e < TB_T * KC * 4; e += NTH) {
            int c4 = e & 3, jj = (e >> 2) % KC, ttl = e / (4 * KC);
            float4 v = __ldg((const float4*)(g_W0T + ((t0 + ttl) * D + kc + jj) * H) + c4);
            ((float4*)&s->w.sW0[ttl][jj][0])[c4] = v;
        }
        // M chunk: read t-contiguous float4s, store mx[j][t][b] (masked, x-scaled)
        for (int e = tid; e < TB_B * KC * (TB_T / 4); e += NTH) {
            int t4 = e % (TB_T / 4);
            int jj = (e / (TB_T / 4)) % KC;
            int b  = e / (KC * (TB_T / 4));
            int gj = kc + jj;
            const float4 m4 =
                __ldg((const float4*)(M + ((size_t)(b0i + b) * D + gj) * D + t0) + t4);
            float xv = s->sX[b][gj];
            float* dst = &s->u.sMX[jj][4 * t4][b];
            int gt = t0 + 4 * t4;
            dst[0 * BPAD] = (gj == gt + 0) ? 0.f : m4.x * xv;
            dst[1 * BPAD] = (gj == gt + 1) ? 0.f : m4.y * xv;
            dst[2 * BPAD] = (gj == gt + 2) ? 0.f : m4.z * xv;
            dst[3 * BPAD] = (gj == gt + 3) ? 0.f : m4.w * xv;
        }
        __syncthreads();
#pragma unroll
        for (int jj = 0; jj < KC; ++jj) {
            const float4 mq  = *(const float4*)&s->u.sMX[jj][tt][4 * bg];
            const float4 wq0 = *(const float4*)&s->w.sW0[tt][jj][8 * ig];
            const float4 wq1 = *(const float4*)&s->w.sW0[tt][jj][8 * ig + 4];
            fma_tile(acc, mq, wq0, wq1);
        }
    }

    __syncthreads();  // done reading sMX/sW0 before unions are repurposed

    // ---- leaky + transpose h0 into smem; stage W1 slice transposed [t][j][i] ----
#pragma unroll
    for (int b = 0; b < 4; ++b)
#pragma unroll
        for (int ip = 0; ip < 4; ++ip) {
            float a, c; unpk2(acc[b][ip], a, c);
            int i = 8 * ig + 2 * ip;
            s->u.sH0[tt][i][4 * bg + b]     = lrelu(a);
            s->u.sH0[tt][i + 1][4 * bg + b] = lrelu(c);
        }
    for (int e = tid; e < TB_T * H * H; e += NTH) {
        int j = e & 15, i = (e >> 4) & 15, ttl = e >> 8;  // e = ttl*256 + i*16 + j
        s->w.sW1[ttl][j][i] = W1g[t0 * H * H + e];
    }
    __syncthreads();

    // ---- layer 1: h1 = leaky(W1 @ h0 + b1), same micro-tile, K=16 ----
    ull acc1[4][4];
    {
        ull bias[4];
#pragma unroll
        for (int ip = 0; ip < 4; ++ip)
            bias[ip] = pk2(s->sB1[tt][8 * ig + 2 * ip], s->sB1[tt][8 * ig + 2 * ip + 1]);
#pragma unroll
        for (int b = 0; b < 4; ++b)
#pragma unroll
            for (int ip = 0; ip < 4; ++ip) acc1[b][ip] = bias[ip];
    }
#pragma unroll
    for (int j = 0; j < H; ++j) {
        const float4 hq  = *(const float4*)&s->u.sH0[tt][j][4 * bg];
        const float4 wq0 = *(const float4*)&s->w.sW1[tt][j][8 * ig];
        const float4 wq1 = *(const float4*)&s->w.sW1[tt][j][8 * ig + 4];
        fma_tile(acc1, hq, wq0, wq1);
    }

    // ---- layer 2: out[b,t,p] = W2[t,p,:] @ h1 + b2 (cross-ig shuffle reduce) ----
    float hv[4][8];
#pragma unroll
    for (int b = 0; b < 4; ++b)
#pragma unroll
        for (int ip = 0; ip < 4; ++ip) {
            float a, c; unpk2(acc1[b][ip], a, c);
            hv[b][2 * ip]     = lrelu(a);
            hv[b][2 * ip + 1] = lrelu(c);
        }
    const int t = t0 + tt;
    float po[4][2];
#pragma unroll
    for (int p = 0; p < 2; ++p) {
        const float4 wa = __ldg((const float4*)&W2g[t * (P * H) + p * H + 8 * ig]);
        const float4 wb = __ldg((const float4*)&W2g[t * (P * H) + p * H + 8 * ig + 4]);
#pragma unroll
        for (int b = 0; b < 4; ++b) {
            float sd = wa.x * hv[b][0];
            sd = fmaf(wa.y, hv[b][1], sd);
            sd = fmaf(wa.z, hv[b][2], sd);
            sd = fmaf(wa.w, hv[b][3], sd);
            sd = fmaf(wb.x, hv[b][4], sd);
            sd = fmaf(wb.y, hv[b][5], sd);
            sd = fmaf(wb.z, hv[b][6], sd);
            sd = fmaf(wb.w, hv[b][7], sd);
            po[b][p] = sd;
        }
    }
#pragma unroll
    for (int b = 0; b < 4; ++b)
#pragma unroll
        for (int p = 0; p < 2; ++p)
            po[b][p] += __shfl_xor_sync(0xffffffffu, po[b][p], 1);
    if (ig == 0) {
        float2 bv = *(const float2*)&b2g[t * 2];
#pragma unroll
        for (int b = 0; b < 4; ++b) {
            float2 o = make_float2(po[b][0] + bv.x, po[b][1] + bv.y);
            ((float2*)out)[(size_t)(b0i + 4 * bg + b) * D + t] = o;
        }
    }
}

extern "C" void kernel_launch(void* const* d_in, const int* in_sizes, int n_in,
                              void* d_out, int out_size) {
    const float* x  = (const float*)d_in[0];
    const float* M  = (const float*)d_in[1];
    const float* W0 = (const float*)d_in[2];
    const float* W1 = (const float*)d_in[3];
    const float* W2 = (const float*)d_in[4];
    const float* b0 = (const float*)d_in[5];
    const float* b1 = (const float*)d_in[6];
    const float* b2 = (const float*)d_in[7];
    float* out = (float*)d_out;

    cudaFuncSetAttribute(mlp_kernel, cudaFuncAttributeMaxDynamicSharedMemorySize,
                         (int)sizeof(Smem));

    transpose_w0_kernel<<<D, 256>>>(W0);
    dim3 grid(BS / TB_B, D / TB_T);
    mlp_kernel<<<grid, NTH, sizeof(Smem)>>>(x, M, W1, W2, b0, b1, b2, out);
}

// round 2
// speedup vs baseline: 1.0714x; 1.0714x over previous
#include <cuda_runtime.h>

typedef unsigned long long ull;

constexpr int BS = 16384, D = 100, H = 16, P = 2;
constexpr int TB_B = 64;     // batch per block (8 warps x 8 b)
constexpr int TB_T = 8;      // t per block (8 t-lanes)
constexpr int NTH  = 256;
constexpr int TPAD = 104;    // t rows in g_W0T (zero-padded)
constexpr int W0S  = 1604;   // smem floats per t-row of W0 (100*16 + 4 pad)
constexpr int W1S  = 260;    // smem floats per t-row of W1 (16*16 + 4 pad)

__device__ float g_W0T[TPAD * D * H];   // [t][j][i]; rows 100..103 = 0
__device__ float g_xT[D * BS];          // [j][b]

// ---- prep kernels ----
__global__ void transpose_w0_kernel(const float* __restrict__ W0) {
    int t = blockIdx.x;  // 0..103
    for (int e = threadIdx.x; e < D * H; e += blockDim.x) {
        int j = e >> 4, i = e & 15;
        g_W0T[t * (D * H) + j * H + i] = (t < D) ? W0[t * (D * H) + i * D + j] : 0.f;
    }
}

__global__ void transpose_x_kernel(const float* __restrict__ x) {
    __shared__ float tile[32][33];
    int bb = blockIdx.x * 32, jb = blockIdx.y * 32;
    int tx = threadIdx.x, ty = threadIdx.y;   // 32 x 8
    for (int r = ty; r < 32; r += 8) {
        int j = jb + tx;
        tile[r][tx] = (j < D) ? x[(bb + r) * D + j] : 0.f;
    }
    __syncthreads();
    for (int r = ty; r < 32; r += 8) {
        int j = jb + r;
        if (j < D) g_xT[j * BS + bb + tx] = tile[tx][r];
    }
}

// ---- helpers ----
__device__ __forceinline__ ull pk2(float a, float b) {
    ull r; asm("mov.b64 %0, {%1, %2};" : "=l"(r) : "f"(a), "f"(b)); return r;
}
__device__ __forceinline__ void unpk2(ull v, float& a, float& b) {
    asm("mov.b64 {%0, %1}, %2;" : "=f"(a), "=f"(b) : "l"(v));
}
__device__ __forceinline__ ull ffma2(ull a, ull b, ull c) {
    ull d; asm("fma.rn.f32x2 %0, %1, %2, %3;" : "=l"(d) : "l"(a), "l"(b), "l"(c));
    return d;
}
__device__ __forceinline__ float lrelu(float v) { return v > 0.f ? v : 0.01f * v; }

// ---- main kernel ----
__global__ void __launch_bounds__(NTH, 2)
mlp_kernel(const float* __restrict__ M, const float* __restrict__ W1g,
           const float* __restrict__ W2g, const float* __restrict__ b0g,
           const float* __restrict__ b1g, const float* __restrict__ b2g,
           float* __restrict__ out) {
    extern __shared__ float smem[];
    float* sW0 = smem;                       // 8 * 1604
    float* sW1 = sW0 + 8 * W0S;              // 8 * 260
    float* sB1 = sW1 + 8 * W1S;              // 8 * 17
    float* sW2 = sB1 + 8 * 17 + 8;           // 8 * 36  (bump keeps 16B align: 136+8=144)
    float* sB2 = sW2 + 8 * 36;               // 16

    const int tid  = threadIdx.x;
    const int lane = tid & 31, w = tid >> 5;
    const int tl = lane & 7, bq = lane >> 3;          // t-lane, b-quad
    const int t0 = blockIdx.y * TB_T;
    const int t  = t0 + tl;
    const bool tv = (t < D);
    const int Bbase = blockIdx.x * TB_B + w * 8 + bq * 2;  // this thread: b = Bbase, Bbase+1

    // ---- stage W0 tile (float4) ----
    {
        const float4* src = reinterpret_cast<const float4*>(g_W0T) + (size_t)t0 * 400;
        float4* dst = reinterpret_cast<float4*>(sW0);
        for (int e = tid; e < 8 * 400; e += NTH) {
            int r = e / 400, c = e - r * 400;
            dst[r * 401 + c] = src[e];
        }
    }
    // ---- stage W1 / b1 / W2 / b2 (guarded for t >= 100) ----
    for (int e = tid; e < 8 * 256; e += NTH) {
        int r = e >> 8, c = e & 255;
        sW1[r * W1S + c] = (t0 + r < D) ? W1g[(t0 + r) * 256 + c] : 0.f;
    }
    if (tid < 128) {
        int r = tid >> 4, c = tid & 15;
        sB1[r * 17 + c] = (t0 + r < D) ? b1g[(t0 + r) * H + c] : 0.f;
    }
    if (tid < 256) {
        int r = tid >> 5, c = tid & 31;
        sW2[r * 36 + c] = (t0 + r < D) ? W2g[(t0 + r) * (P * H) + c] : 0.f;
    }
    if (tid < 16) {
        int r = tid >> 1, c = tid & 1;
        sB2[r * 2 + c] = (t0 + r < D) ? b2g[(t0 + r) * P + c] : 0.f;
    }
    __syncthreads();

    // ---- acc init with b0 ----
    ull acc[2][8];
#pragma unroll
    for (int ip = 0; ip < 8; ++ip) {
        float a = tv ? __ldg(b0g + t * H + 2 * ip)     : 0.f;
        float b = tv ? __ldg(b0g + t * H + 2 * ip + 1) : 0.f;
        ull bb = pk2(a, b);
        acc[0][ip] = bb; acc[1][ip] = bb;
    }

    const float* mp = M + (size_t)Bbase * (D * D) + t;   // + j*D (+ D*D for b+1)
    const float* xp = g_xT + Bbase;                      // + j*BS

    float  mA[2][4], mB[2][4];
    float2 xA[4], xB[4];

#define LOAD_CHUNK(jc, mm, xx)                                                  \
    {                                                                           \
        _Pragma("unroll")                                                       \
        for (int u = 0; u < 4; ++u) {                                           \
            int j = (jc) + u;                                                   \
            mm[0][u] = tv ? __ldg(mp + j * D) : 0.f;                            \
            mm[1][u] = tv ? __ldg(mp + j * D + D * D) : 0.f;                    \
            xx[u] = *reinterpret_cast<const float2*>(xp + (size_t)j * BS);      \
        }                                                                       \
    }

#define COMP_CHUNK(jc, mm, xx)                                                  \
    {                                                                           \
        _Pragma("unroll")                                                       \
        for (int u = 0; u < 4; ++u) {                                           \
            int j = (jc) + u;                                                   \
            const longlong2* wr =                                               \
                reinterpret_cast<const longlong2*>(sW0 + tl * W0S + j * 16);    \
            longlong2 q0 = wr[0], q1 = wr[1], q2 = wr[2], q3 = wr[3];           \
            ull W[8] = {(ull)q0.x, (ull)q0.y, (ull)q1.x, (ull)q1.y,             \
                        (ull)q2.x, (ull)q2.y, (ull)q3.x, (ull)q3.y};            \
            bool nd = (j != t);                                                 \
            float mx0 = nd ? mm[0][u] * xx[u].x : 0.f;                          \
            float mx1 = nd ? mm[1][u] * xx[u].y : 0.f;                          \
            ull p0 = pk2(mx0, mx0), p1 = pk2(mx1, mx1);                         \
            _Pragma("unroll")                                                   \
            for (int ip = 0; ip < 8; ++ip) {                                    \
                acc[0][ip] = ffma2(W[ip], p0, acc[0][ip]);                      \
                acc[1][ip] = ffma2(W[ip], p1, acc[1][ip]);                      \
            }                                                                   \
        }                                                                       \
    }

    // ---- main j loop: 25 chunks of 4, double-buffered ----
    LOAD_CHUNK(0, mA, xA);
#pragma unroll 1
    for (int jc = 0; jc < 96; jc += 8) {
        LOAD_CHUNK(jc + 4, mB, xB);
        COMP_CHUNK(jc, mA, xA);
        LOAD_CHUNK(jc + 8, mA, xA);
        COMP_CHUNK(jc + 4, mB, xB);
    }
    COMP_CHUNK(96, mA, xA);

#undef LOAD_CHUNK
#undef COMP_CHUNK

    // ---- layers 1 & 2 per owned b ----
#pragma unroll
    for (int k = 0; k < 2; ++k) {
        float h0f[16];
#pragma unroll
        for (int ip = 0; ip < 8; ++ip) {
            float a, b; unpk2(acc[k][ip], a, b);
            h0f[2 * ip]     = lrelu(a);
            h0f[2 * ip + 1] = lrelu(b);
        }
        float h1[16];
#pragma unroll
        for (int ii = 0; ii < 16; ++ii) {
            const float4* w1r = reinterpret_cast<const float4*>(sW1 + tl * W1S + ii * 16);
            float4 a = w1r[0], b = w1r[1], c = w1r[2], d = w1r[3];
            float s = sB1[tl * 17 + ii];
            s = fmaf(a.x, h0f[0],  s); s = fmaf(a.y, h0f[1],  s);
            s = fmaf(a.z, h0f[2],  s); s = fmaf(a.w, h0f[3],  s);
            s = fmaf(b.x, h0f[4],  s); s = fmaf(b.y, h0f[5],  s);
            s = fmaf(b.z, h0f[6],  s); s = fmaf(b.w, h0f[7],  s);
            s = fmaf(c.x, h0f[8],  s); s = fmaf(c.y, h0f[9],  s);
            s = fmaf(c.z, h0f[10], s); s = fmaf(c.w, h0f[11], s);
            s = fmaf(d.x, h0f[12], s); s = fmaf(d.y, h0f[13], s);
            s = fmaf(d.z, h0f[14], s); s = fmaf(d.w, h0f[15], s);
            h1[ii] = lrelu(s);
        }
        float po[2];
#pragma unroll
        for (int p = 0; p < 2; ++p) {
            const float4* w2r = reinterpret_cast<const float4*>(sW2 + tl * 36 + p * 16);
            float4 a = w2r[0], b = w2r[1], c = w2r[2], d = w2r[3];
            float s = sB2[tl * 2 + p];
            s = fmaf(a.x, h1[0],  s); s = fmaf(a.y, h1[1],  s);
            s = fmaf(a.z, h1[2],  s); s = fmaf(a.w, h1[3],  s);
            s = fmaf(b.x, h1[4],  s); s = fmaf(b.y, h1[5],  s);
            s = fmaf(b.z, h1[6],  s); s = fmaf(b.w, h1[7],  s);
            s = fmaf(c.x, h1[8],  s); s = fmaf(c.y, h1[9],  s);
            s = fmaf(c.z, h1[10], s); s = fmaf(c.w, h1[11], s);
            s = fmaf(d.x, h1[12], s); s = fmaf(d.y, h1[13], s);
            s = fmaf(d.z, h1[14], s); s = fmaf(d.w, h1[15], s);
            po[p] = s;
        }
        if (tv) {
            float2 o = make_float2(po[0], po[1]);
            *reinterpret_cast<float2*>(out + ((size_t)(Bbase + k) * D + t) * P) = o;
        }
    }
}

extern "C" void kernel_launch(void* const* d_in, const int* in_sizes, int n_in,
                              void* d_out, int out_size) {
    const float* x  = (const float*)d_in[0];
    const float* M  = (const float*)d_in[1];
    const float* W0 = (const float*)d_in[2];
    const float* W1 = (const float*)d_in[3];
    const float* W2 = (const float*)d_in[4];
    const float* b0 = (const float*)d_in[5];
    const float* b1 = (const float*)d_in[6];
    const float* b2 = (const float*)d_in[7];
    float* out = (float*)d_out;

    constexpr int SMEM_BYTES = (8 * W0S + 8 * W1S + 8 * 17 + 8 + 8 * 36 + 16) * 4;
    cudaFuncSetAttribute(mlp_kernel, cudaFuncAttributeMaxDynamicSharedMemorySize,
                         SMEM_BYTES);

    transpose_w0_kernel<<<TPAD, 256>>>(W0);
    transpose_x_kernel<<<dim3(BS / 32, (D + 31) / 32), dim3(32, 8)>>>(x);

    dim3 grid(BS / TB_B, (D + TB_T - 1) / TB_T);   // 256 x 13
    mlp_kernel<<<grid, NTH, SMEM_BYTES>>>(M, W1, W2, b0, b1, b2, out);
}